// round 1
// baseline (speedup 1.0000x reference)
#include <cuda_runtime.h>
#include <cuda_bf16.h>

#define NP 110000
#define NT 20000
#define NG 10000
#define NTOT (NP + NT + NG)   // 140000
#define EE 500000
#define DD 64

// ---- scratch (static device memory; no allocations allowed) ----
__device__ __align__(16) float g_x1[NTOT * DD];   // layer-1 conv output, later final table p
__device__ __align__(16) float g_x2[NTOT * DD];   // layer-2 conv output
__device__ __align__(16) float g_dinv[NTOT];      // degree -> rsqrt(degree)
__device__ __align__(16) float g_norm[3 * EE];    // per-edge norm per graph

// ---------------------------------------------------------------
__global__ void zero_all_kernel() {
    int i = blockIdx.x * blockDim.x + threadIdx.x;
    int stride = gridDim.x * blockDim.x;
    const int n4 = NTOT * DD / 4;
    float4 z = make_float4(0.f, 0.f, 0.f, 0.f);
    for (int j = i; j < n4; j += stride) {
        reinterpret_cast<float4*>(g_x1)[j] = z;
        reinterpret_cast<float4*>(g_x2)[j] = z;
    }
    for (int j = i; j < NTOT; j += stride) g_dinv[j] = 0.f;
}

// accumulate in-degrees for all three graphs (into g_dinv as counts)
__global__ void degree_kernel(const int* __restrict__ up,
                              const int* __restrict__ ut,
                              const int* __restrict__ ug) {
    int i = blockIdx.x * blockDim.x + threadIdx.x;
    if (i < EE) {
        atomicAdd(&g_dinv[up[EE + i]], 1.f);
    } else if (i < 2 * EE) {
        atomicAdd(&g_dinv[NP + ut[EE + (i - EE)]], 1.f);
    } else if (i < 3 * EE) {
        atomicAdd(&g_dinv[NP + NT + ug[EE + (i - 2 * EE)]], 1.f);
    }
}

__global__ void dinv_kernel() {
    int i = blockIdx.x * blockDim.x + threadIdx.x;
    if (i < NTOT) {
        float v = g_dinv[i];
        g_dinv[i] = (v > 0.f) ? rsqrtf(v) : 0.f;
    }
}

// per-edge symmetric norm for all three graphs
__global__ void norm_kernel(const int* __restrict__ up,
                            const int* __restrict__ ut,
                            const int* __restrict__ ug) {
    int i = blockIdx.x * blockDim.x + threadIdx.x;
    if (i < EE) {
        int s = up[i], d = up[EE + i];
        g_norm[i] = g_dinv[s] * g_dinv[d];
    } else if (i < 2 * EE) {
        int e = i - EE;
        int s = ut[e], d = ut[EE + e];
        g_norm[i] = g_dinv[NP + s] * g_dinv[NP + d];
    } else if (i < 3 * EE) {
        int e = i - 2 * EE;
        int s = ug[e], d = ug[EE + e];
        g_norm[i] = g_dinv[NP + NT + s] * g_dinv[NP + NT + d];
    }
}

__device__ __forceinline__ void red_add_v4(float* p, float4 v) {
    asm volatile("red.global.add.v4.f32 [%0], {%1,%2,%3,%4};"
                 :: "l"(p), "f"(v.x), "f"(v.y), "f"(v.z), "f"(v.w) : "memory");
}

// layer-1 conv: reads external embedding table, writes g_x1[base..]
// 16 threads per edge, each moves one float4 (one full 256B row per edge)
__global__ void conv_l1_kernel(const float* __restrict__ emb,
                               const int* __restrict__ edge,
                               int base, int gidx) {
    int tid = blockIdx.x * blockDim.x + threadIdx.x;
    int e = tid >> 4;
    if (e >= EE) return;
    int j = (tid & 15) << 2;
    float w = g_norm[gidx * EE + e];
    if (w == 0.f) return;  // zero contribution (src in-degree 0)
    int s = edge[e], d = edge[EE + e];
    float4 v = *reinterpret_cast<const float4*>(emb + (long)s * DD + j);
    float4 r = make_float4(v.x * w, v.y * w, v.z * w, v.w * w);
    red_add_v4(g_x1 + (long)(base + d) * DD + j, r);
}

// layer-2 conv: reads g_x1, writes g_x2
__global__ void conv_l2_kernel(const int* __restrict__ edge, int base, int gidx) {
    int tid = blockIdx.x * blockDim.x + threadIdx.x;
    int e = tid >> 4;
    if (e >= EE) return;
    int j = (tid & 15) << 2;
    float w = g_norm[gidx * EE + e];
    if (w == 0.f) return;
    int s = edge[e], d = edge[EE + e];
    float4 v = *reinterpret_cast<const float4*>(g_x1 + (long)(base + s) * DD + j);
    float4 r = make_float4(v.x * w, v.y * w, v.z * w, v.w * w);
    red_add_v4(g_x2 + (long)(base + d) * DD + j, r);
}

// p = (emb + x1 + x2) / 3, written in place into g_x1
__global__ void finalize_kernel(const float* __restrict__ emb, int base, int n4) {
    int i = blockIdx.x * blockDim.x + threadIdx.x;
    if (i >= n4) return;
    const float4* e4 = reinterpret_cast<const float4*>(emb);
    float4* x1 = reinterpret_cast<float4*>(g_x1 + (long)base * DD);
    const float4* x2 = reinterpret_cast<const float4*>(g_x2 + (long)base * DD);
    float4 a = e4[i], b = x1[i], c = x2[i];
    const float k = 1.f / 3.f;
    x1[i] = make_float4((a.x + b.x + c.x) * k, (a.y + b.y + c.y) * k,
                        (a.z + b.z + c.z) * k, (a.w + b.w + c.w) * k);
}

// final fused per-edge kernel: feature linears + 6 gathers + dot product
// one warp per edge; lane l owns dims {2l, 2l+1}
__global__ void __launch_bounds__(256)
final_kernel(const int* __restrict__ up, const int* __restrict__ ut,
             const int* __restrict__ ug,
             const float* __restrict__ sfeat, const float* __restrict__ dfeat,
             const float* __restrict__ Ws, const float* __restrict__ bs,
             const float* __restrict__ Wd, const float* __restrict__ bd,
             float* __restrict__ out) {
    __shared__ float sWs[16 * 64];
    __shared__ float sWd[16 * 64];
    __shared__ float sbs[64];
    __shared__ float sbd[64];
    int t = threadIdx.x;
    for (int i = t; i < 1024; i += blockDim.x) { sWs[i] = Ws[i]; sWd[i] = Wd[i]; }
    if (t < 64) { sbs[t] = bs[t]; sbd[t] = bd[t]; }
    __syncthreads();

    int e = (blockIdx.x * blockDim.x + t) >> 5;
    if (e >= EE) return;
    int lane = t & 31;
    int d2 = lane << 1;

    // feature linears: 16 inputs broadcast via shfl, weights from SMEM
    float fsv = sfeat[e * 16 + (lane & 15)];
    float fdv = dfeat[e * 16 + (lane & 15)];
    float fs0 = sbs[d2], fs1 = sbs[d2 + 1];
    float fd0 = sbd[d2], fd1 = sbd[d2 + 1];
#pragma unroll
    for (int k = 0; k < 16; k++) {
        float a = __shfl_sync(0xffffffffu, fsv, k);
        float b = __shfl_sync(0xffffffffu, fdv, k);
        float2 ws = *reinterpret_cast<const float2*>(sWs + k * 64 + d2);
        float2 wd = *reinterpret_cast<const float2*>(sWd + k * 64 + d2);
        fs0 = fmaf(a, ws.x, fs0); fs1 = fmaf(a, ws.y, fs1);
        fd0 = fmaf(b, wd.x, fd0); fd1 = fmaf(b, wd.y, fd1);
    }

    int s0 = up[e], dn0 = up[EE + e];
    int s1 = ut[e], dn1 = ut[EE + e];
    int s2 = ug[e], dn2 = ug[EE + e];
    const float* P = g_x1;
    const float* T = g_x1 + (long)NP * DD;
    const float* G = g_x1 + (long)(NP + NT) * DD;

    float2 ps = *reinterpret_cast<const float2*>(P + (long)s0 * DD + d2);
    float2 ts = *reinterpret_cast<const float2*>(T + (long)s1 * DD + d2);
    float2 gs = *reinterpret_cast<const float2*>(G + (long)s2 * DD + d2);
    float2 pd = *reinterpret_cast<const float2*>(P + (long)dn0 * DD + d2);
    float2 td = *reinterpret_cast<const float2*>(T + (long)dn1 * DD + d2);
    float2 gd = *reinterpret_cast<const float2*>(G + (long)dn2 * DD + d2);

    const float k3 = 1.f / 3.f;
    float os0 = (ps.x + ts.x + gs.x) * k3 + fs0;
    float os1 = (ps.y + ts.y + gs.y) * k3 + fs1;
    float od0 = (pd.x + td.x + gd.x) * k3 + fd0;
    float od1 = (pd.y + td.y + gd.y) * k3 + fd1;

    float partial = os0 * od0 + os1 * od1;
#pragma unroll
    for (int o = 16; o; o >>= 1)
        partial += __shfl_xor_sync(0xffffffffu, partial, o);
    if (lane == 0) out[e] = partial;
}

// ---------------------------------------------------------------
extern "C" void kernel_launch(void* const* d_in, const int* in_sizes, int n_in,
                              void* d_out, int out_size) {
    const int*   up     = (const int*)d_in[0];
    const int*   ut     = (const int*)d_in[1];
    const int*   ug     = (const int*)d_in[2];
    const float* sfeat  = (const float*)d_in[3];
    const float* dfeat  = (const float*)d_in[4];
    const float* up_emb = (const float*)d_in[5];
    const float* ut_emb = (const float*)d_in[6];
    const float* ug_emb = (const float*)d_in[7];
    const float* W_src  = (const float*)d_in[8];
    const float* b_src  = (const float*)d_in[9];
    const float* W_dst  = (const float*)d_in[10];
    const float* b_dst  = (const float*)d_in[11];
    float* out = (float*)d_out;

    zero_all_kernel<<<2048, 256>>>();
    degree_kernel<<<(3 * EE + 255) / 256, 256>>>(up, ut, ug);
    dinv_kernel<<<(NTOT + 255) / 256, 256>>>();
    norm_kernel<<<(3 * EE + 255) / 256, 256>>>(up, ut, ug);

    const int convGrid = (EE * 16 + 255) / 256;
    // layer 1: emb -> x1
    conv_l1_kernel<<<convGrid, 256>>>(up_emb, up, 0, 0);
    conv_l1_kernel<<<convGrid, 256>>>(ut_emb, ut, NP, 1);
    conv_l1_kernel<<<convGrid, 256>>>(ug_emb, ug, NP + NT, 2);
    // layer 2: x1 -> x2
    conv_l2_kernel<<<convGrid, 256>>>(up, 0, 0);
    conv_l2_kernel<<<convGrid, 256>>>(ut, NP, 1);
    conv_l2_kernel<<<convGrid, 256>>>(ug, NP + NT, 2);

    // p = (emb + x1 + x2)/3 into g_x1
    finalize_kernel<<<(NP * 16 + 255) / 256, 256>>>(up_emb, 0, NP * 16);
    finalize_kernel<<<(NT * 16 + 255) / 256, 256>>>(ut_emb, NP, NT * 16);
    finalize_kernel<<<(NG * 16 + 255) / 256, 256>>>(ug_emb, NP + NT, NG * 16);

    // fused edge output: one warp per edge
    final_kernel<<<(EE * 32 + 255) / 256, 256>>>(up, ut, ug, sfeat, dfeat,
                                                 W_src, b_src, W_dst, b_dst, out);
}